// round 7
// baseline (speedup 1.0000x reference)
#include <cuda_runtime.h>

// Fused bilinear 2x up -> leaky_relu(0.01) -> bilinear 0.5x down == 3x3 stencil.
// x, out: (16, 128, 128, 128) fp32 NHWC.
//
// R6 vs R5 (50.3us, regs=80 -> 3 CTAs/SM, occ 32%, latency-bound):
//  - __launch_bounds__(256,4): target 64 regs -> 4 CTAs -> 32 warps/SM
//  - rows r0/r1 and po0/po1 addressed off one pointer with immediate offsets
//    (adjacent rows never clamp against each other) -> 2 fewer pointers
//  - output row r0 fully computed+stored before row-3 hlerp (shrinks peak
//    register liveness: L0/R0/u die before L3/R3 are born)

constexpr int H   = 128;
constexpr int W   = 128;
constexpr int C4  = 32;    // 128 channels / 4
constexpr int WC4 = W * C4;
constexpr int STRIP = 8;   // output columns per thread

// L = 0.25*a + 0.75*b ; R = 0.75*b + 0.25*c  (t = 0.75*b shared)
__device__ __forceinline__ void hlerp(const float4& a, const float4& b, const float4& c,
                                      float4& L, float4& R) {
    float tx = 0.75f * b.x, ty = 0.75f * b.y, tz = 0.75f * b.z, tw = 0.75f * b.w;
    L = make_float4(fmaf(a.x, 0.25f, tx), fmaf(a.y, 0.25f, ty),
                    fmaf(a.z, 0.25f, tz), fmaf(a.w, 0.25f, tw));
    R = make_float4(fmaf(c.x, 0.25f, tx), fmaf(c.y, 0.25f, ty),
                    fmaf(c.z, 0.25f, tz), fmaf(c.w, 0.25f, tw));
}

__device__ __forceinline__ void vlerp(const float4& v0, const float4& v1, const float4& v2,
                                      float4& U0, float4& U1) {
    float tx = 0.75f * v1.x, ty = 0.75f * v1.y, tz = 0.75f * v1.z, tw = 0.75f * v1.w;
    U0 = make_float4(fmaf(v0.x, 0.25f, tx), fmaf(v0.y, 0.25f, ty),
                     fmaf(v0.z, 0.25f, tz), fmaf(v0.w, 0.25f, tw));
    U1 = make_float4(fmaf(v2.x, 0.25f, tx), fmaf(v2.y, 0.25f, ty),
                     fmaf(v2.z, 0.25f, tz), fmaf(v2.w, 0.25f, tw));
}

// out = 0.25 * sum_k leaky(u_k)  ==  0.12625*sum(u) + 0.12375*sum(|u|)
__device__ __forceinline__ float4 corner_sum(const float4& u00, const float4& u01,
                                             const float4& u10, const float4& u11) {
    float4 r;
    {
        float su = (u00.x + u01.x) + (u10.x + u11.x);
        float sa = (fabsf(u00.x) + fabsf(u01.x)) + (fabsf(u10.x) + fabsf(u11.x));
        r.x = fmaf(su, 0.12625f, 0.12375f * sa);
    }
    {
        float su = (u00.y + u01.y) + (u10.y + u11.y);
        float sa = (fabsf(u00.y) + fabsf(u01.y)) + (fabsf(u10.y) + fabsf(u11.y));
        r.y = fmaf(su, 0.12625f, 0.12375f * sa);
    }
    {
        float su = (u00.z + u01.z) + (u10.z + u11.z);
        float sa = (fabsf(u00.z) + fabsf(u01.z)) + (fabsf(u10.z) + fabsf(u11.z));
        r.z = fmaf(su, 0.12625f, 0.12375f * sa);
    }
    {
        float su = (u00.w + u01.w) + (u10.w + u11.w);
        float sa = (fabsf(u00.w) + fabsf(u01.w)) + (fabsf(u10.w) + fabsf(u11.w));
        r.w = fmaf(su, 0.12625f, 0.12375f * sa);
    }
    return r;
}

__global__ __launch_bounds__(256, 4)
void activation_filter_kernel(const float4* __restrict__ x, float4* __restrict__ out) {
    const int r0 = 2 * blockIdx.x;     // output row pair (r0, r0+1 = r0 + WC4 elems)
    const int half = blockIdx.y;       // width half (0: cols 0..63, 1: 64..127)
    const int b  = blockIdx.z;
    const int tid = threadIdx.x;
    const int c4    = tid & 31;
    const int strip = tid >> 5;        // 0..7, warp-uniform
    const int j0    = half * 64 + strip * STRIP;

    const int im = (r0 > 0)         ? r0 - 1 : 0;      // row above r0 (clamped)
    const int iq = (r0 + 1 < H - 1) ? r0 + 2 : H - 1;  // row below r1 (clamped)

    const int img   = b * (H * WC4);
    const int basec = j0 * C4 + c4;
    const float4* __restrict__ pm = x + img + im * WC4 + basec;   // row im
    const float4* __restrict__ p0 = x + img + r0 * WC4 + basec;   // rows r0 (+WC4 -> r1)
    const float4* __restrict__ pq = x + img + iq * WC4 + basec;   // row iq
    float4* __restrict__ po = out + img + r0 * WC4 + basec;       // rows r0 (+WC4 -> r1)

    // window prologue: a = col j0-1 (clamped, warp-uniform), b = col j0
    const int offA = (j0 > 0) ? -C4 : 0;
    float4 a0 = pm[offA], a1 = p0[offA], a2 = p0[offA + WC4], a3 = pq[offA];
    float4 b0 = pm[0],    b1 = p0[0],    b2 = p0[WC4],        b3 = pq[0];

    #pragma unroll
    for (int s = 0; s < STRIP - 1; ++s) {
        // all loads first: 4 independent LDG.128
        float4 c0 = pm[C4];
        float4 c1 = p0[C4];
        float4 c2 = p0[C4 + WC4];
        float4 c3 = pq[C4];

        float4 L0, R0, L1, R1, L2, R2;
        hlerp(a0, b0, c0, L0, R0); a0 = b0; b0 = c0;
        hlerp(a1, b1, c1, L1, R1); a1 = b1; b1 = c1;
        hlerp(a2, b2, c2, L2, R2); a2 = b2; b2 = c2;

        // finish output row r0 before touching row 3 (liveness)
        {
            float4 u00, u10, u01, u11;
            vlerp(L0, L1, L2, u00, u10);
            vlerp(R0, R1, R2, u01, u11);
            __stcs(po, corner_sum(u00, u01, u10, u11));
        }

        float4 L3, R3;
        hlerp(a3, b3, c3, L3, R3); a3 = b3; b3 = c3;
        {
            float4 u00, u10, u01, u11;
            vlerp(L1, L2, L3, u00, u10);
            vlerp(R1, R2, R3, u01, u11);
            __stcs(po + WC4, corner_sum(u00, u01, u10, u11));
        }

        pm += C4; p0 += C4; pq += C4; po += C4;
    }

    // final column of the strip: only the rightmost strip clamps (warp-uniform)
    {
        float4 c0, c1, c2, c3;
        if (j0 + STRIP < W) {
            c0 = pm[C4]; c1 = p0[C4]; c2 = p0[C4 + WC4]; c3 = pq[C4];
        } else {
            c0 = b0; c1 = b1; c2 = b2; c3 = b3;
        }
        float4 L0, R0, L1, R1, L2, R2;
        hlerp(a0, b0, c0, L0, R0);
        hlerp(a1, b1, c1, L1, R1);
        hlerp(a2, b2, c2, L2, R2);
        {
            float4 u00, u10, u01, u11;
            vlerp(L0, L1, L2, u00, u10);
            vlerp(R0, R1, R2, u01, u11);
            __stcs(po, corner_sum(u00, u01, u10, u11));
        }
        float4 L3, R3;
        hlerp(a3, b3, c3, L3, R3);
        {
            float4 u00, u10, u01, u11;
            vlerp(L1, L2, L3, u00, u10);
            vlerp(R1, R2, R3, u01, u11);
            __stcs(po + WC4, corner_sum(u00, u01, u10, u11));
        }
    }
}

extern "C" void kernel_launch(void* const* d_in, const int* in_sizes, int n_in,
                              void* d_out, int out_size) {
    const float4* x = (const float4*)d_in[0];
    float4* out = (float4*)d_out;
    dim3 grid(H / 2, 2, 16);   // (row pair, width half, batch) = 2048 blocks
    activation_filter_kernel<<<grid, 256>>>(x, out);
}

// round 9
// speedup vs baseline: 1.1925x; 1.1925x over previous
#include <cuda_runtime.h>

// Fused bilinear 2x up -> leaky_relu(0.01) -> bilinear 0.5x down == 3x3 stencil.
// x, out: (16, 128, 128, 128) fp32 NHWC.
//
// R7: R6's pointer-dedup + liveness reorder, but back at 3 CTAs/SM.
// R6's __launch_bounds__(256,4) forced regs=64 via local-memory spills
// (L1% 38->59, time 50.3->64.4us). True footprint is ~80 regs; 3 CTAs is
// the correct occupancy point.

constexpr int H   = 128;
constexpr int W   = 128;
constexpr int C4  = 32;    // 128 channels / 4
constexpr int WC4 = W * C4;
constexpr int STRIP = 8;   // output columns per thread

// L = 0.25*a + 0.75*b ; R = 0.75*b + 0.25*c  (t = 0.75*b shared)
__device__ __forceinline__ void hlerp(const float4& a, const float4& b, const float4& c,
                                      float4& L, float4& R) {
    float tx = 0.75f * b.x, ty = 0.75f * b.y, tz = 0.75f * b.z, tw = 0.75f * b.w;
    L = make_float4(fmaf(a.x, 0.25f, tx), fmaf(a.y, 0.25f, ty),
                    fmaf(a.z, 0.25f, tz), fmaf(a.w, 0.25f, tw));
    R = make_float4(fmaf(c.x, 0.25f, tx), fmaf(c.y, 0.25f, ty),
                    fmaf(c.z, 0.25f, tz), fmaf(c.w, 0.25f, tw));
}

__device__ __forceinline__ void vlerp(const float4& v0, const float4& v1, const float4& v2,
                                      float4& U0, float4& U1) {
    float tx = 0.75f * v1.x, ty = 0.75f * v1.y, tz = 0.75f * v1.z, tw = 0.75f * v1.w;
    U0 = make_float4(fmaf(v0.x, 0.25f, tx), fmaf(v0.y, 0.25f, ty),
                     fmaf(v0.z, 0.25f, tz), fmaf(v0.w, 0.25f, tw));
    U1 = make_float4(fmaf(v2.x, 0.25f, tx), fmaf(v2.y, 0.25f, ty),
                     fmaf(v2.z, 0.25f, tz), fmaf(v2.w, 0.25f, tw));
}

// out = 0.25 * sum_k leaky(u_k)  ==  0.12625*sum(u) + 0.12375*sum(|u|)
__device__ __forceinline__ float4 corner_sum(const float4& u00, const float4& u01,
                                             const float4& u10, const float4& u11) {
    float4 r;
    {
        float su = (u00.x + u01.x) + (u10.x + u11.x);
        float sa = (fabsf(u00.x) + fabsf(u01.x)) + (fabsf(u10.x) + fabsf(u11.x));
        r.x = fmaf(su, 0.12625f, 0.12375f * sa);
    }
    {
        float su = (u00.y + u01.y) + (u10.y + u11.y);
        float sa = (fabsf(u00.y) + fabsf(u01.y)) + (fabsf(u10.y) + fabsf(u11.y));
        r.y = fmaf(su, 0.12625f, 0.12375f * sa);
    }
    {
        float su = (u00.z + u01.z) + (u10.z + u11.z);
        float sa = (fabsf(u00.z) + fabsf(u01.z)) + (fabsf(u10.z) + fabsf(u11.z));
        r.z = fmaf(su, 0.12625f, 0.12375f * sa);
    }
    {
        float su = (u00.w + u01.w) + (u10.w + u11.w);
        float sa = (fabsf(u00.w) + fabsf(u01.w)) + (fabsf(u10.w) + fabsf(u11.w));
        r.w = fmaf(su, 0.12625f, 0.12375f * sa);
    }
    return r;
}

__global__ __launch_bounds__(256, 3)
void activation_filter_kernel(const float4* __restrict__ x, float4* __restrict__ out) {
    const int r0 = 2 * blockIdx.x;     // output row pair (r0, r0+1 = +WC4 elems)
    const int half = blockIdx.y;       // width half (0: cols 0..63, 1: 64..127)
    const int b  = blockIdx.z;
    const int tid = threadIdx.x;
    const int c4    = tid & 31;
    const int strip = tid >> 5;        // 0..7, warp-uniform
    const int j0    = half * 64 + strip * STRIP;

    const int im = (r0 > 0)         ? r0 - 1 : 0;      // row above r0 (clamped)
    const int iq = (r0 + 1 < H - 1) ? r0 + 2 : H - 1;  // row below r1 (clamped)

    const int img   = b * (H * WC4);
    const int basec = j0 * C4 + c4;
    const float4* __restrict__ pm = x + img + im * WC4 + basec;   // row im
    const float4* __restrict__ p0 = x + img + r0 * WC4 + basec;   // rows r0 (+WC4 -> r1)
    const float4* __restrict__ pq = x + img + iq * WC4 + basec;   // row iq
    float4* __restrict__ po = out + img + r0 * WC4 + basec;       // rows r0 (+WC4 -> r1)

    // window prologue: a = col j0-1 (clamped, warp-uniform), b = col j0
    const int offA = (j0 > 0) ? -C4 : 0;
    float4 a0 = pm[offA], a1 = p0[offA], a2 = p0[offA + WC4], a3 = pq[offA];
    float4 b0 = pm[0],    b1 = p0[0],    b2 = p0[WC4],        b3 = pq[0];

    #pragma unroll
    for (int s = 0; s < STRIP - 1; ++s) {
        // all loads first: 4 independent LDG.128
        float4 c0 = pm[C4];
        float4 c1 = p0[C4];
        float4 c2 = p0[C4 + WC4];
        float4 c3 = pq[C4];

        float4 L0, R0, L1, R1, L2, R2;
        hlerp(a0, b0, c0, L0, R0); a0 = b0; b0 = c0;
        hlerp(a1, b1, c1, L1, R1); a1 = b1; b1 = c1;
        hlerp(a2, b2, c2, L2, R2); a2 = b2; b2 = c2;

        // finish output row r0 before touching row 3 (liveness)
        {
            float4 u00, u10, u01, u11;
            vlerp(L0, L1, L2, u00, u10);
            vlerp(R0, R1, R2, u01, u11);
            __stcs(po, corner_sum(u00, u01, u10, u11));
        }

        float4 L3, R3;
        hlerp(a3, b3, c3, L3, R3); a3 = b3; b3 = c3;
        {
            float4 u00, u10, u01, u11;
            vlerp(L1, L2, L3, u00, u10);
            vlerp(R1, R2, R3, u01, u11);
            __stcs(po + WC4, corner_sum(u00, u01, u10, u11));
        }

        pm += C4; p0 += C4; pq += C4; po += C4;
    }

    // final column of the strip: only the rightmost strip clamps (warp-uniform)
    {
        float4 c0, c1, c2, c3;
        if (j0 + STRIP < W) {
            c0 = pm[C4]; c1 = p0[C4]; c2 = p0[C4 + WC4]; c3 = pq[C4];
        } else {
            c0 = b0; c1 = b1; c2 = b2; c3 = b3;
        }
        float4 L0, R0, L1, R1, L2, R2;
        hlerp(a0, b0, c0, L0, R0);
        hlerp(a1, b1, c1, L1, R1);
        hlerp(a2, b2, c2, L2, R2);
        {
            float4 u00, u10, u01, u11;
            vlerp(L0, L1, L2, u00, u10);
            vlerp(R0, R1, R2, u01, u11);
            __stcs(po, corner_sum(u00, u01, u10, u11));
        }
        float4 L3, R3;
        hlerp(a3, b3, c3, L3, R3);
        {
            float4 u00, u10, u01, u11;
            vlerp(L1, L2, L3, u00, u10);
            vlerp(R1, R2, R3, u01, u11);
            __stcs(po + WC4, corner_sum(u00, u01, u10, u11));
        }
    }
}

extern "C" void kernel_launch(void* const* d_in, const int* in_sizes, int n_in,
                              void* d_out, int out_size) {
    const float4* x = (const float4*)d_in[0];
    float4* out = (float4*)d_out;
    dim3 grid(H / 2, 2, 16);   // (row pair, width half, batch) = 2048 blocks
    activation_filter_kernel<<<grid, 256>>>(x, out);
}